// round 8
// baseline (speedup 1.0000x reference)
#include <cuda_runtime.h>

#define BB 256
#define AA 128
#define DD 5
#define FATOM 256
#define FBOND 64
#define FTOT 320   // FATOM + FBOND
#define CC 256
#define NROWS (BB * AA)
#define TILE_M 16
#define TILES_X 80
#define NTHREADS 512

typedef unsigned long long ull;

// Scratch (no device allocation allowed anywhere).
__device__ int g_count[DD];
__device__ int g_rows[DD * NROWS];

// ---------------- packed f32x2 helpers (register-only asm) ----------------
__device__ __forceinline__ ull fma2(ull a, ull b, ull c) {
    ull d;
    asm("fma.rn.f32x2 %0, %1, %2, %3;" : "=l"(d) : "l"(a), "l"(b), "l"(c));
    return d;
}
__device__ __forceinline__ void unpack2(ull v, float& lo, float& hi) {
    asm("mov.b64 {%0, %1}, %2;" : "=f"(lo), "=f"(hi) : "l"(v));
}

// Kernel A (fused): per-row degree; deg==5 rows -> zero output row;
// deg<5 rows -> append to deg-list. Warp handles 4 rows via ballot.
// Append order varies but each row handled exactly once -> deterministic.
__global__ void __launch_bounds__(256) classify_zero_kernel(
    const int* __restrict__ edges, float4* __restrict__ out4)
{
    const int wid  = threadIdx.x >> 5;
    const int lane = threadIdx.x & 31;
    const int rbase = blockIdx.x * 32 + wid * 4;
    const float4 z = make_float4(0.f, 0.f, 0.f, 0.f);

#pragma unroll
    for (int i = 0; i < 4; i++) {
        const int row = rbase + i;
        int e = -1;
        if (lane < DD) e = edges[row * DD + lane];
        unsigned m = __ballot_sync(0xffffffffu, (lane < DD) && (e >= 0));
        int deg = __popc(m);
        if (deg == DD) {
            float4* o = out4 + row * (CC / 4);
            o[lane] = z;
            o[lane + 32] = z;
        } else if (lane == 0) {
            int pos = atomicAdd(&g_count[deg], 1);
            g_rows[deg * NROWS + pos] = row;
        }
    }
}

// Kernel B: per-deg grouped GEMM.
// Tile = 16 rows x 256 cols, 512 threads: cp = tid&127 -> cols 2cp,2cp+1;
// rq = tid>>7 -> rows rq*4..rq*4+3. feat stored DUPLICATED ((v,v) u64) so
// fma.rn.f32x2 operands come from broadcast LDS.128 (compiler-visible
// ulonglong2 loads -> schedulable) with zero packing movs. W read directly
// (LDG.64, coalesced, L2-resident) with one-step register prefetch.
__global__ void __launch_bounds__(NTHREADS) gemm_kernel(
    const float4* __restrict__ atoms4, const float4* __restrict__ bonds4,
    const int* __restrict__ edges, const float* __restrict__ W,
    const float* __restrict__ bias, float* __restrict__ out)
{
    __shared__ ull featd[TILE_M][FTOT];   // duplicated feat: 40 KB

    const int deg = blockIdx.y;
    const int count = g_count[deg];
    if (count == 0) return;

    const int tid  = threadIdx.x;
    const int wid  = tid >> 5;    // 0..15, one warp per feat row
    const int lane = tid & 31;
    const int cp   = tid & 127;   // cols 2cp, 2cp+1
    const int rq   = tid >> 7;    // rows rq*4 .. rq*4+3
    const ull* __restrict__ Wp =
        reinterpret_cast<const ull*>(W + deg * FTOT * CC) + cp;
    const ull bv2 = *reinterpret_cast<const ull*>(&bias[deg * CC + 2 * cp]);

    for (int tile = blockIdx.x; tile * TILE_M < count; tile += gridDim.x) {
        const int base  = tile * TILE_M;
        const int nrows = min(TILE_M, count - base);

        __syncthreads();  // prior-iteration feat readers done

        // ---- Feat build (duplicated): warp 'wid' builds row 'wid' ----
        if (wid < nrows) {
            const int row   = g_rows[deg * NROWS + base + wid];
            const int bbase = (row >> 7) << 7;  // b * AA
            int e[DD];
#pragma unroll
            for (int d = 0; d < DD; d++) e[d] = edges[row * DD + d];
#pragma unroll
            for (int k = 0; k < 2; k++) {
                const int f4 = lane + 32 * k;      // float4 idx (f = 4*f4)
                float4 v = atoms4[row * 64 + f4];
#pragma unroll
                for (int d = 0; d < DD; d++) {
                    if (e[d] >= 0) {
                        float4 nv = atoms4[(bbase + e[d]) * 64 + f4];
                        v.x += nv.x; v.y += nv.y; v.z += nv.z; v.w += nv.w;
                    }
                }
                float4* dst = reinterpret_cast<float4*>(&featd[wid][4 * f4]);
                dst[0] = make_float4(v.x, v.x, v.y, v.y);
                dst[1] = make_float4(v.z, v.z, v.w, v.w);
            }
            if (lane < 16) {
                float4 s = make_float4(0.f, 0.f, 0.f, 0.f);
#pragma unroll
                for (int d = 0; d < DD; d++) {
                    float4 bvv = bonds4[(row * DD + d) * 16 + lane];
                    s.x += bvv.x; s.y += bvv.y; s.z += bvv.z; s.w += bvv.w;
                }
                float4* dst = reinterpret_cast<float4*>(&featd[wid][FATOM + 4 * lane]);
                dst[0] = make_float4(s.x, s.x, s.y, s.y);
                dst[1] = make_float4(s.z, s.z, s.w, s.w);
            }
        }
        __syncthreads();

        // ---- GEMM: 4 rows x 2 cols per thread, W prefetched 1 step ahead ----
        ull acc[4];
#pragma unroll
        for (int r = 0; r < 4; r++) acc[r] = bv2;

        const ull* wp = Wp;
        ull w0 = wp[0 * (CC / 2)];
        ull w1 = wp[1 * (CC / 2)];
        ull w2 = wp[2 * (CC / 2)];
        ull w3 = wp[3 * (CC / 2)];
        wp += 4 * (CC / 2);

#pragma unroll 4
        for (int f = 0; f < FTOT; f += 4) {
            // branchless prefetch (clamped: last step re-reads same block)
            const ull* np = (f + 4 < FTOT) ? wp : wp - 4 * (CC / 2);
            ull n0 = np[0 * (CC / 2)];
            ull n1 = np[1 * (CC / 2)];
            ull n2 = np[2 * (CC / 2)];
            ull n3 = np[3 * (CC / 2)];
            wp += 4 * (CC / 2);

#pragma unroll
            for (int r = 0; r < 4; r++) {
                const ulonglong2* fr = reinterpret_cast<const ulonglong2*>(
                    &featd[rq * 4 + r][f]);
                const ulonglong2 p01 = fr[0];   // dup feat f, f+1
                const ulonglong2 p23 = fr[1];   // dup feat f+2, f+3
                acc[r] = fma2(p01.x, w0, acc[r]);
                acc[r] = fma2(p01.y, w1, acc[r]);
                acc[r] = fma2(p23.x, w2, acc[r]);
                acc[r] = fma2(p23.y, w3, acc[r]);
            }
            w0 = n0; w1 = n1; w2 = n2; w3 = n3;
        }

        // ---- Epilogue: relu + float2 store per row ----
#pragma unroll
        for (int r = 0; r < 4; r++) {
            const int ri = rq * 4 + r;
            if (ri < nrows) {
                const int row = g_rows[deg * NROWS + base + ri];
                float lo, hi;
                unpack2(acc[r], lo, hi);
                float2 o = make_float2(fmaxf(lo, 0.f), fmaxf(hi, 0.f));
                *reinterpret_cast<float2*>(&out[row * CC + 2 * cp]) = o;
            }
        }
    }
}

extern "C" void kernel_launch(void* const* d_in, const int* in_sizes, int n_in,
                              void* d_out, int out_size) {
    const float* atoms = (const float*)d_in[0];   // (B, A, FA) f32
    const float* bonds = (const float*)d_in[1];   // (B, A, D, FB) f32
    const int*   edges = (const int*)d_in[2];     // (B, A, D) i32
    const float* W     = (const float*)d_in[3];   // (D, FA+FB, C) f32
    const float* bias  = (const float*)d_in[4];   // (D, C) f32
    float* out = (float*)d_out;                   // (B, A, C) f32

    // Reset compaction counters (memset node; no allocation).
    void* cnt_addr = nullptr;
    cudaGetSymbolAddress(&cnt_addr, g_count);
    cudaMemsetAsync(cnt_addr, 0, DD * sizeof(int));

    classify_zero_kernel<<<NROWS / 32, 256>>>(edges, (float4*)out);
    // grid: x = tile slots (stride loop), y = deg
    gemm_kernel<<<dim3(TILES_X, DD), NTHREADS>>>((const float4*)atoms,
                                                 (const float4*)bonds,
                                                 edges, W, bias, out);
}

// round 13
// speedup vs baseline: 1.2878x; 1.2878x over previous
#include <cuda_runtime.h>

#define BB 256
#define AA 128
#define DD 5
#define FATOM 256
#define FBOND 64
#define FTOT 320   // FATOM + FBOND
#define CC 256
#define CH 128                // columns per C-half
#define NROWS (BB * AA)
#define TILE_M 16

// Scratch (no device allocation allowed anywhere).
__device__ int g_count[DD];
__device__ int g_rows[DD * NROWS];

// Kernel A (fused): per-row degree; deg==5 rows -> zero output row;
// deg<5 rows -> append to deg-list. Warp handles 4 rows via ballot.
// Append order varies but each row handled exactly once -> deterministic.
__global__ void __launch_bounds__(256) classify_zero_kernel(
    const int* __restrict__ edges, float4* __restrict__ out4)
{
    const int wid  = threadIdx.x >> 5;
    const int lane = threadIdx.x & 31;
    const int rbase = blockIdx.x * 32 + wid * 4;
    const float4 z = make_float4(0.f, 0.f, 0.f, 0.f);

#pragma unroll
    for (int i = 0; i < 4; i++) {
        const int row = rbase + i;
        int e = -1;
        if (lane < DD) e = edges[row * DD + lane];
        unsigned m = __ballot_sync(0xffffffffu, (lane < DD) && (e >= 0));
        int deg = __popc(m);
        if (deg == DD) {
            float4* o = out4 + row * (CC / 4);
            o[lane] = z;
            o[lane + 32] = z;
        } else if (lane == 0) {
            int pos = atomicAdd(&g_count[deg], 1);
            g_rows[deg * NROWS + pos] = row;
        }
    }
}

// Kernel B: per-deg grouped GEMM, plain FFMA, no asm.
// Grid (2, 80, DD): x = C-half, y = tile slot (stride loop), z = deg.
// Block 256 threads: cl = tid&127 -> one column (chalf*128 + cl);
// rg = tid>>7 -> rows rg*8 .. rg*8+7.  feat is plain float smem; reads are
// warp-broadcast float4.  W read directly from L2 (warp = 128B contiguous
// per f-row), register-prefetched one 4-step ahead.
__global__ void __launch_bounds__(256) gemm_kernel(
    const float4* __restrict__ atoms4, const float4* __restrict__ bonds4,
    const int* __restrict__ edges, const float* __restrict__ W,
    const float* __restrict__ bias, float* __restrict__ out)
{
    __shared__ float feat[TILE_M][FTOT];   // 20 KB

    const int deg = blockIdx.z;
    const int count = g_count[deg];
    if (count == 0) return;

    const int tid  = threadIdx.x;
    const int wid  = tid >> 5;
    const int lane = tid & 31;
    const int cl   = tid & 127;                 // column within half
    const int rg   = tid >> 7;                  // 0/1 -> rows rg*8..rg*8+7
    const int col  = blockIdx.x * CH + cl;      // global column
    const float* __restrict__ Wc = W + deg * FTOT * CC + col;
    const float bv = bias[deg * CC + col];

    for (int tile = blockIdx.y; tile * TILE_M < count; tile += gridDim.y) {
        const int base  = tile * TILE_M;
        const int nrows = min(TILE_M, count - base);

        __syncthreads();  // prior-iteration feat readers done

        // ---- Feat build: warp 'wid' builds rows wid and wid+8 ----
#pragma unroll
        for (int rr = 0; rr < 2; rr++) {
            const int r = wid + rr * 8;
            if (r < nrows) {
                const int row   = g_rows[deg * NROWS + base + r];
                const int bbase = (row >> 7) << 7;  // b * AA
                int e[DD];
#pragma unroll
                for (int d = 0; d < DD; d++) e[d] = edges[row * DD + d];
#pragma unroll
                for (int k = 0; k < 2; k++) {
                    const int f4 = lane + 32 * k;   // float4 index (f = 4*f4)
                    float4 v = atoms4[row * 64 + f4];
#pragma unroll
                    for (int d = 0; d < DD; d++) {
                        if (e[d] >= 0) {
                            float4 nv = atoms4[(bbase + e[d]) * 64 + f4];
                            v.x += nv.x; v.y += nv.y; v.z += nv.z; v.w += nv.w;
                        }
                    }
                    *reinterpret_cast<float4*>(&feat[r][4 * f4]) = v;
                }
                if (lane < 16) {
                    float4 s = make_float4(0.f, 0.f, 0.f, 0.f);
#pragma unroll
                    for (int d = 0; d < DD; d++) {
                        float4 bvv = bonds4[(row * DD + d) * 16 + lane];
                        s.x += bvv.x; s.y += bvv.y; s.z += bvv.z; s.w += bvv.w;
                    }
                    *reinterpret_cast<float4*>(&feat[r][FATOM + 4 * lane]) = s;
                }
            }
        }
        __syncthreads();

        // ---- GEMM: 8 rows x 1 col per thread, plain FFMA ----
        float acc[8];
#pragma unroll
        for (int r = 0; r < 8; r++) acc[r] = bv;

        // register prefetch, distance one 4-step
        float w0 = Wc[0 * CC];
        float w1 = Wc[1 * CC];
        float w2 = Wc[2 * CC];
        float w3 = Wc[3 * CC];

        for (int f = 0; f < FTOT; f += 4) {
            const int nf = (f + 4 < FTOT) ? f + 4 : f;   // clamp on last step
            const float n0 = Wc[(nf + 0) * CC];
            const float n1 = Wc[(nf + 1) * CC];
            const float n2 = Wc[(nf + 2) * CC];
            const float n3 = Wc[(nf + 3) * CC];

#pragma unroll
            for (int r = 0; r < 8; r++) {
                const float4 fv = *reinterpret_cast<const float4*>(
                    &feat[rg * 8 + r][f]);
                acc[r] = fmaf(fv.x, w0, acc[r]);
                acc[r] = fmaf(fv.y, w1, acc[r]);
                acc[r] = fmaf(fv.z, w2, acc[r]);
                acc[r] = fmaf(fv.w, w3, acc[r]);
            }
            w0 = n0; w1 = n1; w2 = n2; w3 = n3;
        }

        // ---- Epilogue: relu + scatter (warp writes 128B per row) ----
#pragma unroll
        for (int r = 0; r < 8; r++) {
            const int ri = rg * 8 + r;
            if (ri < nrows) {
                const int row = g_rows[deg * NROWS + base + ri];
                out[row * CC + col] = fmaxf(acc[r], 0.f);
            }
        }
    }
}

extern "C" void kernel_launch(void* const* d_in, const int* in_sizes, int n_in,
                              void* d_out, int out_size) {
    const float* atoms = (const float*)d_in[0];   // (B, A, FA) f32
    const float* bonds = (const float*)d_in[1];   // (B, A, D, FB) f32
    const int*   edges = (const int*)d_in[2];     // (B, A, D) i32
    const float* W     = (const float*)d_in[3];   // (D, FA+FB, C) f32
    const float* bias  = (const float*)d_in[4];   // (D, C) f32
    float* out = (float*)d_out;                   // (B, A, C) f32

    // Reset compaction counters (memset node; no allocation).
    void* cnt_addr = nullptr;
    cudaGetSymbolAddress(&cnt_addr, g_count);
    cudaMemsetAsync(cnt_addr, 0, DD * sizeof(int));

    classify_zero_kernel<<<NROWS / 32, 256>>>(edges, (float4*)out);
    // grid: x = C-half, y = tile slots (stride loop), z = deg
    gemm_kernel<<<dim3(2, 80, DD), 256>>>((const float4*)atoms,
                                          (const float4*)bonds,
                                          edges, W, bias, out);
}

// round 17
// speedup vs baseline: 1.3693x; 1.0633x over previous
#include <cuda_runtime.h>

#define BB 256
#define AA 128
#define DD 5
#define FATOM 256
#define FBOND 64
#define FTOT 320   // FATOM + FBOND
#define CC 256
#define NROWS (BB * AA)
#define TILE_M 16
#define TILES_X 80

typedef unsigned long long ull;

// Scratch (no device allocation allowed anywhere).
__device__ int g_count[DD];
__device__ int g_rows[DD * NROWS];

// ---------------- packed f32x2 helpers ----------------
__device__ __forceinline__ ull pack2(float lo, float hi) {
    ull r;
    asm("mov.b64 %0, {%1, %2};" : "=l"(r) : "f"(lo), "f"(hi));
    return r;
}
__device__ __forceinline__ void unpack2(ull v, float& lo, float& hi) {
    asm("mov.b64 {%0, %1}, %2;" : "=f"(lo), "=f"(hi) : "l"(v));
}
__device__ __forceinline__ ull fma2(ull a, ull b, ull c) {
    ull d;
    asm("fma.rn.f32x2 %0, %1, %2, %3;" : "=l"(d) : "l"(a), "l"(b), "l"(c));
    return d;
}

// Kernel A (fused): per-row degree; deg==5 rows -> zero output row
// (one-hot mask over 0..4 is all-zero there); deg<5 rows -> append to
// deg-list. Warp handles 4 rows via ballot. Append order varies but each
// row is handled exactly once, independently -> deterministic output.
__global__ void __launch_bounds__(256) classify_zero_kernel(
    const int* __restrict__ edges, float4* __restrict__ out4)
{
    const int wid  = threadIdx.x >> 5;
    const int lane = threadIdx.x & 31;
    const int rbase = blockIdx.x * 32 + wid * 4;
    const float4 z = make_float4(0.f, 0.f, 0.f, 0.f);

#pragma unroll
    for (int i = 0; i < 4; i++) {
        const int row = rbase + i;
        int e = -1;
        if (lane < DD) e = edges[row * DD + lane];
        unsigned m = __ballot_sync(0xffffffffu, (lane < DD) && (e >= 0));
        int deg = __popc(m);
        if (deg == DD) {
            float4* o = out4 + row * (CC / 4);
            o[lane] = z;        // 64 float4 per row, 2 per lane, coalesced
            o[lane + 32] = z;
        } else if (lane == 0) {
            int pos = atomicAdd(&g_count[deg], 1);
            g_rows[deg * NROWS + pos] = row;
        }
    }
}

// Kernel B: per-deg grouped GEMM — EXACT copy of the best-measured (33.3us
// total) version. Tile = 16 rows x 256 cols, 256 threads: cp = tid&127 ->
// cols 2cp,2cp+1; rg = tid>>7 -> rows rg*8..rg*8+7. feat staged in smem;
// W read directly from L2 as ull (packed col pair); packed fma.rn.f32x2.
__global__ void __launch_bounds__(256) gemm_kernel(
    const float4* __restrict__ atoms4, const float4* __restrict__ bonds4,
    const int* __restrict__ edges, const float* __restrict__ W,
    const float* __restrict__ bias, float* __restrict__ out)
{
    __shared__ float feat[TILE_M][FTOT];  // 16 * 320 * 4 = 20 KB
    const int deg = blockIdx.y;
    const int count = g_count[deg];
    if (count == 0) return;

    const int tid  = threadIdx.x;
    const int wid  = tid >> 5;
    const int lane = tid & 31;
    const int cp   = tid & 127;   // column pair -> cols 2cp, 2cp+1
    const int rg   = tid >> 7;    // row group: rows rg*8 .. rg*8+7
    const float* Wd = W + deg * FTOT * CC;
    const ull bv2 =
        *reinterpret_cast<const ull*>(&bias[deg * CC + 2 * cp]);

    for (int tile = blockIdx.x; tile * TILE_M < count; tile += gridDim.x) {
        const int base  = tile * TILE_M;
        const int nrows = min(TILE_M, count - base);

        __syncthreads();  // protect feat from previous iteration readers

        // ---- Feat build: warp 'wid' builds rows wid and wid+8 ----
#pragma unroll
        for (int rr = 0; rr < 2; rr++) {
            const int r = wid + rr * 8;
            if (r < nrows) {
                const int row   = g_rows[deg * NROWS + base + r];
                const int bbase = (row >> 7) << 7;  // b * AA
                int e[DD];
#pragma unroll
                for (int d = 0; d < DD; d++) e[d] = edges[row * DD + d];

                // atom part: 256 floats = 64 float4; lanes cover 32, k=0..1
#pragma unroll
                for (int k = 0; k < 2; k++) {
                    const int f4 = lane + 32 * k;
                    float4 v = atoms4[row * 64 + f4];
#pragma unroll
                    for (int d = 0; d < DD; d++) {
                        if (e[d] >= 0) {
                            float4 nv = atoms4[(bbase + e[d]) * 64 + f4];
                            v.x += nv.x; v.y += nv.y; v.z += nv.z; v.w += nv.w;
                        }
                    }
                    *reinterpret_cast<float4*>(&feat[r][f4 * 4]) = v;
                }
                // bond part: 64 floats = 16 float4; lanes 0..15
                if (lane < 16) {
                    float4 s = make_float4(0.f, 0.f, 0.f, 0.f);
#pragma unroll
                    for (int d = 0; d < DD; d++) {
                        float4 bvv = bonds4[(row * DD + d) * 16 + lane];
                        s.x += bvv.x; s.y += bvv.y; s.z += bvv.z; s.w += bvv.w;
                    }
                    *reinterpret_cast<float4*>(&feat[r][FATOM + lane * 4]) = s;
                }
            }
        }
        __syncthreads();

        // ---- GEMM: 8 rows x 2 cols per thread, packed fma.rn.f32x2 ----
        ull acc[8];
#pragma unroll
        for (int r = 0; r < 8; r++) acc[r] = bv2;

        const ull* wc = reinterpret_cast<const ull*>(Wd + 2 * cp);
        // wc[f * (CC/2)] == W[f][2cp..2cp+1]
        for (int f = 0; f < FTOT; f += 4) {
            ull w0 = wc[(f + 0) * (CC / 2)];
            ull w1 = wc[(f + 1) * (CC / 2)];
            ull w2 = wc[(f + 2) * (CC / 2)];
            ull w3 = wc[(f + 3) * (CC / 2)];
#pragma unroll
            for (int r = 0; r < 8; r++) {
                const float4 fv =
                    *reinterpret_cast<const float4*>(&feat[rg * 8 + r][f]);
                acc[r] = fma2(pack2(fv.x, fv.x), w0, acc[r]);
                acc[r] = fma2(pack2(fv.y, fv.y), w1, acc[r]);
                acc[r] = fma2(pack2(fv.z, fv.z), w2, acc[r]);
                acc[r] = fma2(pack2(fv.w, fv.w), w3, acc[r]);
            }
        }

        // ---- Epilogue: relu + scatter ----
#pragma unroll
        for (int r = 0; r < 8; r++) {
            const int ri = rg * 8 + r;
            if (ri < nrows) {
                const int row = g_rows[deg * NROWS + base + ri];
                float lo, hi;
                unpack2(acc[r], lo, hi);
                float2 o = make_float2(fmaxf(lo, 0.f), fmaxf(hi, 0.f));
                *reinterpret_cast<float2*>(&out[row * CC + 2 * cp]) = o;
            }
        }
    }
}

extern "C" void kernel_launch(void* const* d_in, const int* in_sizes, int n_in,
                              void* d_out, int out_size) {
    const float* atoms = (const float*)d_in[0];   // (B, A, FA) f32
    const float* bonds = (const float*)d_in[1];   // (B, A, D, FB) f32
    const int*   edges = (const int*)d_in[2];     // (B, A, D) i32
    const float* W     = (const float*)d_in[3];   // (D, FA+FB, C) f32
    const float* bias  = (const float*)d_in[4];   // (D, C) f32
    float* out = (float*)d_out;                   // (B, A, C) f32

    // Reset compaction counters (memset node; no allocation).
    void* cnt_addr = nullptr;
    cudaGetSymbolAddress(&cnt_addr, g_count);
    cudaMemsetAsync(cnt_addr, 0, DD * sizeof(int));

    classify_zero_kernel<<<NROWS / 32, 256>>>(edges, (float4*)out);
    // grid: x = tile slots (stride loop), y = deg
    gemm_kernel<<<dim3(TILES_X, DD), 256>>>((const float4*)atoms,
                                            (const float4*)bonds,
                                            edges, W, bias, out);
}